// round 8
// baseline (speedup 1.0000x reference)
#include <cuda_runtime.h>
#include <math.h>

// ---------------------------------------------------------------------------
// Actor_Soft_Attention: B=65536, IN=128, HID=256, OUT=8
//
//   agents[b,n] = [s0 | s_{n+1}]  (n=0,1), dim 256
//   h_n = relu(agents_n @ W1^T + b1)         (shared half: t0 = s0 @ W1a^T)
//   e_n = relu(agents_n @ W2^T + b2)
//   a   = softmax over n (2-way, per channel)
//   h_i = a0*h_0 + a1*h_1
//   x   = relu([h_i | s0 s1 s2] @ W3^T + b3)   (K=640 -> 256)
//   out = tanh(x @ W4^T + b4)                  (256 -> 8)
//
// One fused kernel. BM=64 rows per block, 256 threads.
// A_s[64][644] holds the full layer-3 operand: cols [0,256)=h_i (written by
// phase 1), cols [256,640)=state. Weights streamed through SMEM tiles.
// ---------------------------------------------------------------------------

#define BM 64
#define AS 644                 // A_s row stride (640 + 4 pad)
#define WS 132                 // weight tile row stride (128 + 4 pad)
#define XS 66                  // xs tile row stride (64 + 2 pad)

#define A_FLOATS   (BM * AS)           // 41216
#define W_OFF      A_FLOATS
#define W_FLOATS   (2 * 32 * WS)       // 8448 (two 32x128 halves)
#define XS_OFF     (W_OFF + W_FLOATS)  // 49664
#define XS_FLOATS  (32 * XS)           // 2112
#define W4_OFF     (XS_OFF + XS_FLOATS)// 51776
#define W4_FLOATS  2048
#define SMEM_FLOATS (W4_OFF + W4_FLOATS) // 53824
#define SMEM_BYTES  (SMEM_FLOATS * 4)    // 215296 bytes

__device__ __forceinline__ float dot4(float4 a, float4 w, float acc) {
    acc = fmaf(a.x, w.x, acc);
    acc = fmaf(a.y, w.y, acc);
    acc = fmaf(a.z, w.z, acc);
    acc = fmaf(a.w, w.w, acc);
    return acc;
}

__global__ __launch_bounds__(256, 1)
void actor_soft_attention_kernel(
    const float* __restrict__ state,
    const float* __restrict__ W1, const float* __restrict__ b1,
    const float* __restrict__ W2, const float* __restrict__ b2,
    const float* __restrict__ W3, const float* __restrict__ b3,
    const float* __restrict__ W4, const float* __restrict__ b4,
    float* __restrict__ out)
{
    extern __shared__ float sm[];
    float* A_s  = sm;            // [64][644]
    float* W_s  = sm + W_OFF;    // [2][32][132]
    float* xs_s = sm + XS_OFF;   // [32][66]
    float* W4t  = sm + W4_OFF;   // [256][8]  (W4 transposed)

    const int t  = threadIdx.x;
    const int tr = t & 15;       // row group: rows tr + 16*i, i=0..3
    const int tc = t >> 4;       // ch group:  channels tc, tc+16 within a 32-tile
    const long long row_base = (long long)blockIdx.x * BM;

    // --- W4 transposed into smem: W4t[j*8+o] = W4[o*256+j] ---
    for (int i = t; i < 2048; i += 256) {
        int o = i >> 8, j = i & 255;
        W4t[j * 8 + o] = W4[i];
    }

    // --- state tile -> A_s[r][256..639] (tile is contiguous 64*384 floats) ---
    {
        const float4* gs = (const float4*)(state + row_base * 384);
        for (int i4 = t; i4 < 6144; i4 += 256) {
            int r = i4 / 96;
            int q = (i4 % 96) * 4;
            float4 v = gs[i4];
            *(float4*)&A_s[r * AS + 256 + q] = v;
        }
    }
    __syncthreads();

    // =====================================================================
    // Phase 1: layer 1 (W1, W2) + 2-way softmax combine -> h_i into A_s[:,0:256)
    // =====================================================================
    for (int c0 = 0; c0 < 256; c0 += 32) {
        // ---- stage W1 tile: rows c0..c0+31, split into [:,0:128) and [:,128:256) ----
        {
            const float4* gw = (const float4*)(W1 + (size_t)c0 * 256);
            for (int i4 = t; i4 < 2048; i4 += 256) {
                int ch = i4 >> 6;
                int d  = (i4 & 63) * 4;
                float4 v = gw[i4];
                int part = d >> 7;
                int dd   = d & 127;
                *(float4*)&W_s[part * (32 * WS) + ch * WS + dd] = v;
            }
        }
        __syncthreads();

        float t0[4][2] = {}, t1[4][2] = {}, t2[4][2] = {};
        #pragma unroll 4
        for (int k = 0; k < 128; k += 4) {
            float4 wa0 = *(float4*)&W_s[tc * WS + k];
            float4 wa1 = *(float4*)&W_s[(tc + 16) * WS + k];
            float4 wb0 = *(float4*)&W_s[32 * WS + tc * WS + k];
            float4 wb1 = *(float4*)&W_s[32 * WS + (tc + 16) * WS + k];
            #pragma unroll
            for (int i = 0; i < 4; i++) {
                const float* ap = &A_s[(tr + 16 * i) * AS];
                float4 a0 = *(float4*)&ap[256 + k];
                float4 a1 = *(float4*)&ap[384 + k];
                float4 a2 = *(float4*)&ap[512 + k];
                t0[i][0] = dot4(a0, wa0, t0[i][0]);
                t0[i][1] = dot4(a0, wa1, t0[i][1]);
                t1[i][0] = dot4(a1, wb0, t1[i][0]);
                t1[i][1] = dot4(a1, wb1, t1[i][1]);
                t2[i][0] = dot4(a2, wb0, t2[i][0]);
                t2[i][1] = dot4(a2, wb1, t2[i][1]);
            }
        }
        __syncthreads();

        // ---- stage W2 tile (same layout) ----
        {
            const float4* gw = (const float4*)(W2 + (size_t)c0 * 256);
            for (int i4 = t; i4 < 2048; i4 += 256) {
                int ch = i4 >> 6;
                int d  = (i4 & 63) * 4;
                float4 v = gw[i4];
                int part = d >> 7;
                int dd   = d & 127;
                *(float4*)&W_s[part * (32 * WS) + ch * WS + dd] = v;
            }
        }
        __syncthreads();

        float u0[4][2] = {}, u1[4][2] = {}, u2[4][2] = {};
        #pragma unroll 4
        for (int k = 0; k < 128; k += 4) {
            float4 wa0 = *(float4*)&W_s[tc * WS + k];
            float4 wa1 = *(float4*)&W_s[(tc + 16) * WS + k];
            float4 wb0 = *(float4*)&W_s[32 * WS + tc * WS + k];
            float4 wb1 = *(float4*)&W_s[32 * WS + (tc + 16) * WS + k];
            #pragma unroll
            for (int i = 0; i < 4; i++) {
                const float* ap = &A_s[(tr + 16 * i) * AS];
                float4 a0 = *(float4*)&ap[256 + k];
                float4 a1 = *(float4*)&ap[384 + k];
                float4 a2 = *(float4*)&ap[512 + k];
                u0[i][0] = dot4(a0, wa0, u0[i][0]);
                u0[i][1] = dot4(a0, wa1, u0[i][1]);
                u1[i][0] = dot4(a1, wb0, u1[i][0]);
                u1[i][1] = dot4(a1, wb1, u1[i][1]);
                u2[i][0] = dot4(a2, wb0, u2[i][0]);
                u2[i][1] = dot4(a2, wb1, u2[i][1]);
            }
        }

        // ---- combine: relu, 2-way softmax over neighbors, write h_i ----
        float b1v0 = __ldg(&b1[c0 + tc]);
        float b1v1 = __ldg(&b1[c0 + tc + 16]);
        float b2v0 = __ldg(&b2[c0 + tc]);
        float b2v1 = __ldg(&b2[c0 + tc + 16]);
        #pragma unroll
        for (int i = 0; i < 4; i++) {
            #pragma unroll
            for (int j = 0; j < 2; j++) {
                float bb1 = j ? b1v1 : b1v0;
                float bb2 = j ? b2v1 : b2v0;
                float h0 = fmaxf(t0[i][j] + t1[i][j] + bb1, 0.0f);
                float h1 = fmaxf(t0[i][j] + t2[i][j] + bb1, 0.0f);
                float e0 = fmaxf(u0[i][j] + u1[i][j] + bb2, 0.0f);
                float e1 = fmaxf(u0[i][j] + u2[i][j] + bb2, 0.0f);
                float m  = fmaxf(e0, e1);
                float p0 = __expf(e0 - m);
                float p1 = __expf(e1 - m);
                float hi = (p0 * h0 + p1 * h1) / (p0 + p1);
                A_s[(tr + 16 * i) * AS + c0 + tc + 16 * j] = hi;
            }
        }
        __syncthreads();   // W_s reuse + h_i visibility
    }

    // =====================================================================
    // Phase 2 (W3, K=640) fused with Phase 3 (W4 -> 8 outputs, tanh)
    // =====================================================================
    float oacc0 = 0.0f, oacc1 = 0.0f;
    const int p0i = 2 * t;
    const int pr  = p0i >> 3;          // row 0..63 (same for both outputs)
    const int po0 = p0i & 7;
    const int po1 = (p0i + 1) & 7;

    for (int c0 = 0; c0 < 256; c0 += 32) {
        float x[4][2] = {};
        for (int k0 = 0; k0 < 640; k0 += 128) {
            // stage W3 chunk: rows c0..c0+31, cols k0..k0+127
            for (int i4 = t; i4 < 1024; i4 += 256) {
                int ch = i4 >> 5;
                int d  = (i4 & 31) * 4;
                float4 v = *(const float4*)&W3[(size_t)(c0 + ch) * 640 + k0 + d];
                *(float4*)&W_s[ch * WS + d] = v;
            }
            __syncthreads();
            #pragma unroll 4
            for (int k = 0; k < 128; k += 4) {
                float4 w0 = *(float4*)&W_s[tc * WS + k];
                float4 w1 = *(float4*)&W_s[(tc + 16) * WS + k];
                #pragma unroll
                for (int i = 0; i < 4; i++) {
                    float4 a = *(float4*)&A_s[(tr + 16 * i) * AS + k0 + k];
                    x[i][0] = dot4(a, w0, x[i][0]);
                    x[i][1] = dot4(a, w1, x[i][1]);
                }
            }
            __syncthreads();
        }
        // relu + bias, stage this 32-channel slice of xxx as [ch][row]
        float b3v0 = __ldg(&b3[c0 + tc]);
        float b3v1 = __ldg(&b3[c0 + tc + 16]);
        #pragma unroll
        for (int i = 0; i < 4; i++) {
            xs_s[tc * XS + tr + 16 * i]        = fmaxf(x[i][0] + b3v0, 0.0f);
            xs_s[(tc + 16) * XS + tr + 16 * i] = fmaxf(x[i][1] + b3v1, 0.0f);
        }
        __syncthreads();
        // phase-3 partial: out[r][o] += sum_j W4[o][c0+j] * xxx[r][c0+j]
        #pragma unroll
        for (int jj = 0; jj < 32; jj++) {
            float xv = xs_s[jj * XS + pr];
            oacc0 = fmaf(W4t[(c0 + jj) * 8 + po0], xv, oacc0);
            oacc1 = fmaf(W4t[(c0 + jj) * 8 + po1], xv, oacc1);
        }
        __syncthreads();
    }

    float r0 = tanhf(oacc0 + __ldg(&b4[po0]));
    float r1 = tanhf(oacc1 + __ldg(&b4[po1]));
    out[(row_base + pr) * 8 + po0] = r0;
    out[(row_base + pr) * 8 + po1] = r1;
}

// ---------------------------------------------------------------------------
// kernel_launch — graph-capturable, allocation-free.
// Input order (metadata): state, W1, b1, W2, b2, W3, b3, W4, b4
// ---------------------------------------------------------------------------
extern "C" void kernel_launch(void* const* d_in, const int* in_sizes, int n_in,
                              void* d_out, int out_size)
{
    const float* state = (const float*)d_in[0];
    const float* W1    = (const float*)d_in[1];
    const float* b1    = (const float*)d_in[2];
    const float* W2    = (const float*)d_in[3];
    const float* b2    = (const float*)d_in[4];
    const float* W3    = (const float*)d_in[5];
    const float* b3    = (const float*)d_in[6];
    const float* W4    = (const float*)d_in[7];
    const float* b4    = (const float*)d_in[8];
    float* out = (float*)d_out;

    const int B = in_sizes[0] / 384;          // 65536
    const int nblocks = B / BM;               // 1024

    // Idempotent; executes immediately (not a captured stream op).
    cudaFuncSetAttribute(actor_soft_attention_kernel,
                         cudaFuncAttributeMaxDynamicSharedMemorySize,
                         SMEM_BYTES);

    actor_soft_attention_kernel<<<nblocks, 256, SMEM_BYTES>>>(
        state, W1, b1, W2, b2, W3, b3, W4, b4, out);
}

// round 9
// speedup vs baseline: 1.6494x; 1.6494x over previous
#include <cuda_runtime.h>
#include <math.h>

// ---------------------------------------------------------------------------
// Actor_Soft_Attention: B=65536, IN=128, HID=256, OUT=8  (fp32, FFMA2 path)
//
// Per block: 64 batch rows, 256 threads, one fused kernel.
//   Phase 1: h/e GEMVs via shared-agent decomposition (t0 = s0*Wa shared),
//            two-way softmax folded to a sigmoid, h_i written into A_s[:,0:256).
//   Phase 2: x = relu([h_i|s] @ W3^T + b3), 8x4 micro-tile, N in 2 halves.
//   Phase 3: out = tanh(x @ W4^T + b4), fused per N-half.
//
// All inner products use packed fma.rn.f32x2 (SASS FFMA2): accumulators hold
// (even-k, odd-k) partial pairs; operands loaded as ulonglong2 straight from
// K-major smem tiles (no pack instructions).
// ---------------------------------------------------------------------------

#define BM   64
#define AS   644     // A_s row stride: 644*4 % 128 == 16 -> conflict-free row spread
#define W1S  132     // phase-1 W tile stride (128 + 4)
#define W3S  68      // phase-2 W tile stride (64 + 4)
#define XSS  66      // xs stride (64 + 2)

#define A_FLOATS   (BM * AS)              // 41216
#define W_OFF      A_FLOATS
#define W_FLOATS   8704                   // max(64*132=8448, 128*68=8704); xs 128*66=8448 fits
#define W4_OFF     (W_OFF + W_FLOATS)     // 49920
#define SMEM_FLOATS (W4_OFF + 2048)       // 51968
#define SMEM_BYTES  (SMEM_FLOATS * 4)     // 207872 bytes

typedef unsigned long long u64;

// packed dual-FMA: d(lo,hi) += a(lo,hi) * b(lo,hi)   [SASS FFMA2]
__device__ __forceinline__ void ffma2(u64& d, u64 a, u64 b) {
    asm("fma.rn.f32x2 %0, %1, %2, %0;" : "+l"(d) : "l"(a), "l"(b));
}
__device__ __forceinline__ float usum(u64 v) {
    return __uint_as_float((unsigned)v) + __uint_as_float((unsigned)(v >> 32));
}

// acc[i][j] += sum_k A_s[(tr+16i)*AS + abase + k] * W_s[(tc+16j)*W1S + k], k=0..127
__device__ __forceinline__ void gemm1_one(u64 acc[4][4], const float* __restrict__ A_s,
                                          const float* __restrict__ W_s,
                                          int tr, int tc, int abase) {
    #pragma unroll 4
    for (int k = 0; k < 128; k += 4) {
        ulonglong2 w[4];
        #pragma unroll
        for (int j = 0; j < 4; j++)
            w[j] = *(const ulonglong2*)&W_s[(tc + 16 * j) * W1S + k];
        #pragma unroll
        for (int i = 0; i < 4; i++) {
            ulonglong2 a = *(const ulonglong2*)&A_s[(tr + 16 * i) * AS + abase + k];
            #pragma unroll
            for (int j = 0; j < 4; j++) {
                ffma2(acc[i][j], a.x, w[j].x);
                ffma2(acc[i][j], a.y, w[j].y);
            }
        }
    }
}

// two accumulator sets sharing the W tile: segments at abase 384 and 512
__device__ __forceinline__ void gemm1_two(u64 c1[4][4], u64 c2[4][4],
                                          const float* __restrict__ A_s,
                                          const float* __restrict__ W_s,
                                          int tr, int tc) {
    #pragma unroll 4
    for (int k = 0; k < 128; k += 4) {
        ulonglong2 w[4];
        #pragma unroll
        for (int j = 0; j < 4; j++)
            w[j] = *(const ulonglong2*)&W_s[(tc + 16 * j) * W1S + k];
        #pragma unroll
        for (int i = 0; i < 4; i++) {
            const float* ap = &A_s[(tr + 16 * i) * AS];
            ulonglong2 a1 = *(const ulonglong2*)&ap[384 + k];
            ulonglong2 a2 = *(const ulonglong2*)&ap[512 + k];
            #pragma unroll
            for (int j = 0; j < 4; j++) {
                ffma2(c1[i][j], a1.x, w[j].x);
                ffma2(c1[i][j], a1.y, w[j].y);
                ffma2(c2[i][j], a2.x, w[j].x);
                ffma2(c2[i][j], a2.y, w[j].y);
            }
        }
    }
}

__global__ __launch_bounds__(256, 1)
void actor_soft_attention_kernel(
    const float* __restrict__ state,
    const float* __restrict__ W1, const float* __restrict__ b1,
    const float* __restrict__ W2, const float* __restrict__ b2,
    const float* __restrict__ W3, const float* __restrict__ b3,
    const float* __restrict__ W4, const float* __restrict__ b4,
    float* __restrict__ out)
{
    extern __shared__ float sm[];
    float* A_s = sm;             // [64][644]: cols [0,256)=h_i, [256,640)=state
    float* W_s = sm + W_OFF;     // weight tile / xs staging (8704 floats)
    float* W4t = sm + W4_OFF;    // [256][8] W4 transposed

    const int t = threadIdx.x;
    const long long row_base = (long long)blockIdx.x * BM;

    // --- W4 transposed ---
    for (int i = t; i < 2048; i += 256) {
        int o = i >> 8, j = i & 255;
        W4t[j * 8 + o] = W4[i];
    }

    // --- state tile -> A_s[r][256..639] ---
    {
        const float4* gs = (const float4*)(state + row_base * 384);
        for (int i4 = t; i4 < 6144; i4 += 256) {
            int r = i4 / 96;
            int q = (i4 % 96) * 4;
            *(float4*)&A_s[r * AS + 256 + q] = gs[i4];
        }
    }
    __syncthreads();

    // =====================================================================
    // Phase 1: 64-channel tiles. For each tile: W2 passes -> attention coeff,
    // then W1 passes -> h_i (uses att), written into A_s[:,c0..c0+63].
    // =====================================================================
    const int tr = t & 15;        // rows tr + 16i
    const int tc = t >> 4;        // channels tc + 16j within the 64-tile

    for (int c0 = 0; c0 < 256; c0 += 64) {
        float att[4][4];
        u64 p0[4][4], p1[4][4], p2[4][4];

        // ---------- W2 (e) ----------
        #pragma unroll
        for (int i = 0; i < 4; i++)
            #pragma unroll
            for (int j = 0; j < 4; j++) { p0[i][j] = 0; p1[i][j] = 0; p2[i][j] = 0; }

        for (int i4 = t; i4 < 2048; i4 += 256) {                 // Wa (dims 0..127)
            int ch = i4 >> 5, d = (i4 & 31) * 4;
            *(float4*)&W_s[ch * W1S + d] = *(const float4*)&W2[(size_t)(c0 + ch) * 256 + d];
        }
        __syncthreads();
        gemm1_one(p0, A_s, W_s, tr, tc, 256);                    // u0 = s0 . Wa
        __syncthreads();
        for (int i4 = t; i4 < 2048; i4 += 256) {                 // Wb (dims 128..255)
            int ch = i4 >> 5, d = (i4 & 31) * 4;
            *(float4*)&W_s[ch * W1S + d] = *(const float4*)&W2[(size_t)(c0 + ch) * 256 + 128 + d];
        }
        __syncthreads();
        gemm1_two(p1, p2, A_s, W_s, tr, tc);                     // u1, u2

        {
            float b2v[4];
            #pragma unroll
            for (int j = 0; j < 4; j++) b2v[j] = __ldg(&b2[c0 + tc + 16 * j]);
            #pragma unroll
            for (int i = 0; i < 4; i++)
                #pragma unroll
                for (int j = 0; j < 4; j++) {
                    float u0 = usum(p0[i][j]);
                    float e0 = fmaxf(u0 + usum(p1[i][j]) + b2v[j], 0.0f);
                    float e1 = fmaxf(u0 + usum(p2[i][j]) + b2v[j], 0.0f);
                    att[i][j] = __fdividef(1.0f, 1.0f + __expf(e1 - e0));  // softmax weight of n=0
                }
        }
        __syncthreads();

        // ---------- W1 (h) ----------
        #pragma unroll
        for (int i = 0; i < 4; i++)
            #pragma unroll
            for (int j = 0; j < 4; j++) { p0[i][j] = 0; p1[i][j] = 0; p2[i][j] = 0; }

        for (int i4 = t; i4 < 2048; i4 += 256) {
            int ch = i4 >> 5, d = (i4 & 31) * 4;
            *(float4*)&W_s[ch * W1S + d] = *(const float4*)&W1[(size_t)(c0 + ch) * 256 + d];
        }
        __syncthreads();
        gemm1_one(p0, A_s, W_s, tr, tc, 256);                    // t0
        __syncthreads();
        for (int i4 = t; i4 < 2048; i4 += 256) {
            int ch = i4 >> 5, d = (i4 & 31) * 4;
            *(float4*)&W_s[ch * W1S + d] = *(const float4*)&W1[(size_t)(c0 + ch) * 256 + 128 + d];
        }
        __syncthreads();
        gemm1_two(p1, p2, A_s, W_s, tr, tc);                     // t1, t2

        {
            float b1v[4];
            #pragma unroll
            for (int j = 0; j < 4; j++) b1v[j] = __ldg(&b1[c0 + tc + 16 * j]);
            #pragma unroll
            for (int i = 0; i < 4; i++)
                #pragma unroll
                for (int j = 0; j < 4; j++) {
                    float t0 = usum(p0[i][j]);
                    float h0 = fmaxf(t0 + usum(p1[i][j]) + b1v[j], 0.0f);
                    float h1 = fmaxf(t0 + usum(p2[i][j]) + b1v[j], 0.0f);
                    float hi = fmaf(att[i][j], h0 - h1, h1);
                    A_s[(tr + 16 * i) * AS + c0 + tc + 16 * j] = hi;
                }
        }
        __syncthreads();
    }

    // =====================================================================
    // Phase 2 (W3, K=640) in two N-halves of 128, fused with phase 3 (W4).
    // 8 rows x 4 channels per thread.
    // =====================================================================
    const int rg = t & 7;          // rows rg + 8i, i=0..7
    const int cg = t >> 3;         // channels cg + 32j, j=0..3 within the half

    float oacc0 = 0.0f, oacc1 = 0.0f;
    const int pr  = t >> 2;        // output row 0..63
    const int po0 = (2 * t) & 7;
    const int po1 = po0 + 1;

    for (int n0 = 0; n0 < 256; n0 += 128) {
        u64 x[8][4];
        #pragma unroll
        for (int i = 0; i < 8; i++)
            #pragma unroll
            for (int j = 0; j < 4; j++) x[i][j] = 0;

        for (int k0 = 0; k0 < 640; k0 += 64) {
            // stage W3 rows n0..n0+127, cols k0..k0+63
            for (int i4 = t; i4 < 2048; i4 += 256) {
                int ch = i4 >> 4, d = (i4 & 15) * 4;
                *(float4*)&W_s[ch * W3S + d] =
                    *(const float4*)&W3[(size_t)(n0 + ch) * 640 + k0 + d];
            }
            __syncthreads();
            #pragma unroll 4
            for (int k = 0; k < 64; k += 4) {
                ulonglong2 w[4];
                #pragma unroll
                for (int j = 0; j < 4; j++)
                    w[j] = *(const ulonglong2*)&W_s[(cg + 32 * j) * W3S + k];
                #pragma unroll
                for (int i = 0; i < 8; i++) {
                    ulonglong2 a = *(const ulonglong2*)&A_s[(rg + 8 * i) * AS + k0 + k];
                    #pragma unroll
                    for (int j = 0; j < 4; j++) {
                        ffma2(x[i][j], a.x, w[j].x);
                        ffma2(x[i][j], a.y, w[j].y);
                    }
                }
            }
            __syncthreads();   // W_s reuse (and final: frees W_s for xs)
        }

        // relu+bias, stage xxx slice as [ch][row] in the (now free) W_s buffer
        {
            float b3v[4];
            #pragma unroll
            for (int j = 0; j < 4; j++) b3v[j] = __ldg(&b3[n0 + cg + 32 * j]);
            #pragma unroll
            for (int i = 0; i < 8; i++)
                #pragma unroll
                for (int j = 0; j < 4; j++)
                    W_s[(cg + 32 * j) * XSS + rg + 8 * i] =
                        fmaxf(usum(x[i][j]) + b3v[j], 0.0f);
        }
        __syncthreads();

        // phase-3 partial over this 128-channel half
        #pragma unroll 8
        for (int jj = 0; jj < 128; jj++) {
            float xv = W_s[jj * XSS + pr];
            oacc0 = fmaf(W4t[(n0 + jj) * 8 + po0], xv, oacc0);
            oacc1 = fmaf(W4t[(n0 + jj) * 8 + po1], xv, oacc1);
        }
        __syncthreads();
    }

    out[(row_base + pr) * 8 + po0] = tanhf(oacc0 + __ldg(&b4[po0]));
    out[(row_base + pr) * 8 + po1] = tanhf(oacc1 + __ldg(&b4[po1]));
}

// ---------------------------------------------------------------------------
// kernel_launch — graph-capturable, allocation-free.
// Input order (metadata): state, W1, b1, W2, b2, W3, b3, W4, b4
// ---------------------------------------------------------------------------
extern "C" void kernel_launch(void* const* d_in, const int* in_sizes, int n_in,
                              void* d_out, int out_size)
{
    const float* state = (const float*)d_in[0];
    const float* W1    = (const float*)d_in[1];
    const float* b1    = (const float*)d_in[2];
    const float* W2    = (const float*)d_in[3];
    const float* b2    = (const float*)d_in[4];
    const float* W3    = (const float*)d_in[5];
    const float* b3    = (const float*)d_in[6];
    const float* W4    = (const float*)d_in[7];
    const float* b4    = (const float*)d_in[8];
    float* out = (float*)d_out;

    const int B = in_sizes[0] / 384;          // 65536
    const int nblocks = B / BM;               // 1024

    cudaFuncSetAttribute(actor_soft_attention_kernel,
                         cudaFuncAttributeMaxDynamicSharedMemorySize,
                         SMEM_BYTES);

    actor_soft_attention_kernel<<<nblocks, 256, SMEM_BYTES>>>(
        state, W1, b1, W2, b2, W3, b3, W4, b4, out);
}

// round 11
// speedup vs baseline: 8.4795x; 5.1408x over previous
#include <cuda_runtime.h>
#include <cuda_fp16.h>
#include <math.h>
#include <stdint.h>

// ---------------------------------------------------------------------------
// Actor_Soft_Attention: B=65536, IN=128, HID=256, OUT=8
// mma.sync (m16n8k16, fp16 in / fp32 acc) — compiles for plain compute_103.
//
//  pre-kernel: W1,W2 (2 K-chunks each), W3 (5 K-chunks) -> fp16 [256][136] pads
//  main (512 CTAs x 128 rows, 256 thr):
//    stage state -> smem fp16 tiles s0,s1,s2 [128][136]
//    L1 per 64-ch chunk: u-pass (W2) -> att, t-pass (W1) -> h_i fp16 tiles
//       (shared s0*Wa term; 2-way softmax folded to sigmoid)
//    L3: x[128x256] over K=640 = {h0,h1,s0,s1,s2}, N chunks of 128
//    L4: out = tanh(x @ W4^T + b4) via one m16n8k16 tile per warp per chunk
// ---------------------------------------------------------------------------

#define TSB     272                    // row stride bytes (136 halves)
#define TILE_HB 34816                  // 128x136 halves = bytes per tile
#define NCTA    512

#define SM_A    0                      // 5 tiles: h0,h1,s0,s1,s2
#define SM_W    (5 * TILE_HB)          // 174080: W stage / xs buffer
#define SM_W4H  (SM_W + TILE_HB)       // 208896: [2][8][136] fp16 W4
#define SM_BIAS (SM_W4H + 4352)        // 213248: 776 floats (b1|b2|b3|b4)
#define SMEM_BYTES (SM_BIAS + 3104)    // 216352

__device__ __align__(16) __half g_w_f16[9 * 256 * 136];   // 9 chunks [256][136]

// ---------------- warp-level primitives ----------------
__device__ __forceinline__ uint32_t smem_u32(const void* p) {
    uint32_t a;
    asm("{ .reg .u64 t; cvta.to.shared.u64 t, %1; cvt.u32.u64 %0, t; }" : "=r"(a) : "l"(p));
    return a;
}
__device__ __forceinline__ void ldsm4(uint32_t* r, uint32_t a) {
    asm volatile("ldmatrix.sync.aligned.m8n8.x4.shared.b16 {%0,%1,%2,%3}, [%4];"
        : "=r"(r[0]), "=r"(r[1]), "=r"(r[2]), "=r"(r[3]) : "r"(a));
}
__device__ __forceinline__ void ldsm2(uint32_t* r, uint32_t a) {
    asm volatile("ldmatrix.sync.aligned.m8n8.x2.shared.b16 {%0,%1}, [%2];"
        : "=r"(r[0]), "=r"(r[1]) : "r"(a));
}
__device__ __forceinline__ void mma16816(float (&c)[4], const uint32_t a[4],
                                         uint32_t b0, uint32_t b1) {
    asm volatile("mma.sync.aligned.m16n8k16.row.col.f32.f16.f16.f32 "
        "{%0,%1,%2,%3}, {%4,%5,%6,%7}, {%8,%9}, {%0,%1,%2,%3};"
        : "+f"(c[0]), "+f"(c[1]), "+f"(c[2]), "+f"(c[3])
        : "r"(a[0]), "r"(a[1]), "r"(a[2]), "r"(a[3]), "r"(b0), "r"(b1));
}

// C[32 x NT8*8] += A(32 rows,K=128) * W(NT8*8 rows,K=128)^T
template<int NT8>
__device__ __forceinline__ void wgemm1(float (&acc)[2][NT8][4],
                                       uint32_t a_base, uint32_t b_base) {
    #pragma unroll
    for (int kb = 0; kb < 8; kb++) {
        uint32_t af[2][4], bf[NT8 / 2][4];
        ldsm4(af[0], a_base + kb * 32);
        ldsm4(af[1], a_base + 16 * TSB + kb * 32);
        #pragma unroll
        for (int p = 0; p < NT8 / 2; p++)
            ldsm4(bf[p], b_base + p * 16 * TSB + kb * 32);
        #pragma unroll
        for (int i = 0; i < 2; i++)
            #pragma unroll
            for (int j = 0; j < NT8; j++)
                mma16816(acc[i][j], af[i], bf[j >> 1][(j & 1) * 2], bf[j >> 1][(j & 1) * 2 + 1]);
    }
}

// two A tiles sharing one W tile
__device__ __forceinline__ void wgemm2(float (&c1)[2][4][4], float (&c2)[2][4][4],
                                       uint32_t a1, uint32_t a2, uint32_t b_base) {
    #pragma unroll
    for (int kb = 0; kb < 8; kb++) {
        uint32_t f1[2][4], f2[2][4], bf[2][4];
        ldsm4(f1[0], a1 + kb * 32);
        ldsm4(f1[1], a1 + 16 * TSB + kb * 32);
        ldsm4(f2[0], a2 + kb * 32);
        ldsm4(f2[1], a2 + 16 * TSB + kb * 32);
        ldsm4(bf[0], b_base + kb * 32);
        ldsm4(bf[1], b_base + 16 * TSB + kb * 32);
        #pragma unroll
        for (int i = 0; i < 2; i++)
            #pragma unroll
            for (int j = 0; j < 4; j++) {
                uint32_t b0 = bf[j >> 1][(j & 1) * 2], b1 = bf[j >> 1][(j & 1) * 2 + 1];
                mma16816(c1[i][j], f1[i], b0, b1);
                mma16816(c2[i][j], f2[i], b0, b1);
            }
    }
}

// ---------------- weight pre-conversion ----------------
__global__ void convert_weights(const float* __restrict__ W1, const float* __restrict__ W2,
                                const float* __restrict__ W3)
{
    const int c = blockIdx.x, t = threadIdx.x;
    const float* src; int ld, koff;
    if (c < 2)      { src = W1; ld = 256; koff = c * 128; }
    else if (c < 4) { src = W2; ld = 256; koff = (c - 2) * 128; }
    else            { src = W3; ld = 640; koff = (c - 4) * 128; }
    __half* dst = g_w_f16 + (size_t)c * 256 * 136;
    for (int i = t; i < 8192; i += 256) {
        int r = i >> 5, kq = (i & 31) * 4;
        float4 v = *(const float4*)(src + (size_t)r * ld + koff + kq);
        __half* d = dst + r * 136 + kq;
        *(__half2*)d       = __floats2half2_rn(v.x, v.y);
        *(__half2*)(d + 2) = __floats2half2_rn(v.z, v.w);
    }
}

// ---------------- main kernel ----------------
__global__ __launch_bounds__(256, 1)
void actor_main(const float* __restrict__ state,
                const float* __restrict__ b1, const float* __restrict__ b2,
                const float* __restrict__ b3, const float* __restrict__ W4,
                const float* __restrict__ b4, float* __restrict__ out)
{
    extern __shared__ char smem[];
    const uint32_t sb = smem_u32(smem);
    const int t = threadIdx.x, wid = t >> 5, l = t & 31;
    const int wm = wid & 3, wn = wid >> 2;
    const int g = l >> 2, tq = l & 3;
    const int cta = blockIdx.x;

    // ldmatrix per-lane address offsets (bytes)
    const uint32_t a_off = ((l & 7) + ((l >> 3) & 1) * 8) * TSB + (l >> 4) * 16;
    const uint32_t b_off = ((l & 7) + ((l >> 4) & 1) * 8) * TSB + ((l >> 3) & 1) * 16;
    const uint32_t b_off2 = (l & 7) * TSB + ((l >> 3) & 1) * 16;

    // ---- init staging: state -> s-tiles, W4 -> fp16, biases ----
    {
        const float4* gs = (const float4*)(state + (size_t)cta * 128 * 384);
        for (int i4 = t; i4 < 12288; i4 += 256) {
            int r = i4 / 96, cq = (i4 % 96) * 4;
            float4 v = gs[i4];
            __half* d = (__half*)(smem + SM_A + (2 + (cq >> 7)) * TILE_HB
                                  + r * TSB + (cq & 127) * 2);
            *(__half2*)d       = __floats2half2_rn(v.x, v.y);
            *(__half2*)(d + 2) = __floats2half2_rn(v.z, v.w);
        }
        __half* w4h = (__half*)(smem + SM_W4H);
        for (int i = t; i < 2048; i += 256) {
            int o = i >> 8, k = i & 255;
            w4h[((k >> 7) * 8 + o) * 136 + (k & 127)] = __float2half(W4[i]);
        }
        float* bs = (float*)(smem + SM_BIAS);
        for (int i = t; i < 776; i += 256)
            bs[i] = (i < 256) ? b1[i] : (i < 512) ? b2[i - 256]
                  : (i < 768) ? b3[i - 512] : b4[i - 768];
    }
    const float* bs = (const float*)(smem + SM_BIAS);

    // =====================================================================
    // L1: per 64-channel chunk: att from W2, then h_i from W1
    // =====================================================================
    const uint32_t aS0 = sb + SM_A + 2 * TILE_HB + wm * 32 * TSB + a_off;
    const uint32_t aS1 = aS0 + TILE_HB, aS2 = aS0 + 2 * TILE_HB;

    for (int c0 = 0; c0 < 4; c0++) {
        const uint32_t bWa = sb + SM_W + wn * 32 * TSB + b_off;
        const uint32_t bWb = bWa + 64 * TSB;

        // stage W2a|W2b (chunks 2,3), rows c0*64..+63 each
        __syncthreads();
        {
            const float4* sA = (const float4*)(g_w_f16 + (size_t)2 * 256 * 136 + (size_t)c0 * 64 * 136);
            const float4* sB = (const float4*)(g_w_f16 + (size_t)3 * 256 * 136 + (size_t)c0 * 64 * 136);
            float4* d = (float4*)(smem + SM_W);
            for (int i = t; i < 2176; i += 256)
                d[i] = (i < 1088) ? sA[i] : sB[i - 1088];
        }
        __syncthreads();

        float u0[2][4][4] = {}, u1[2][4][4] = {}, u2[2][4][4] = {};
        wgemm1<4>(u0, aS0, bWa);
        wgemm2(u1, u2, aS1, aS2, bWb);

        float b2v[4][2], att[2][4][4];
        #pragma unroll
        for (int j = 0; j < 4; j++) {
            b2v[j][0] = bs[256 + c0 * 64 + wn * 32 + j * 8 + 2 * tq];
            b2v[j][1] = bs[256 + c0 * 64 + wn * 32 + j * 8 + 2 * tq + 1];
        }
        #pragma unroll
        for (int i = 0; i < 2; i++)
            #pragma unroll
            for (int j = 0; j < 4; j++)
                #pragma unroll
                for (int e = 0; e < 4; e++) {
                    float e0 = fmaxf(u0[i][j][e] + u1[i][j][e] + b2v[j][e & 1], 0.0f);
                    float e1 = fmaxf(u0[i][j][e] + u2[i][j][e] + b2v[j][e & 1], 0.0f);
                    att[i][j][e] = __fdividef(1.0f, 1.0f + __expf(e1 - e0));
                }

        // stage W1a|W1b (chunks 0,1)
        __syncthreads();
        {
            const float4* sA = (const float4*)(g_w_f16 + (size_t)0 * 256 * 136 + (size_t)c0 * 64 * 136);
            const float4* sB = (const float4*)(g_w_f16 + (size_t)1 * 256 * 136 + (size_t)c0 * 64 * 136);
            float4* d = (float4*)(smem + SM_W);
            for (int i = t; i < 2176; i += 256)
                d[i] = (i < 1088) ? sA[i] : sB[i - 1088];
        }
        __syncthreads();

        float t0a[2][4][4] = {}, t1a[2][4][4] = {}, t2a[2][4][4] = {};
        wgemm1<4>(t0a, aS0, bWa);
        wgemm2(t1a, t2a, aS1, aS2, bWb);

        float b1v[4][2];
        #pragma unroll
        for (int j = 0; j < 4; j++) {
            b1v[j][0] = bs[c0 * 64 + wn * 32 + j * 8 + 2 * tq];
            b1v[j][1] = bs[c0 * 64 + wn * 32 + j * 8 + 2 * tq + 1];
        }
        #pragma unroll
        for (int i = 0; i < 2; i++)
            #pragma unroll
            for (int j = 0; j < 4; j++) {
                int colg = c0 * 64 + wn * 32 + j * 8 + 2 * tq;
                #pragma unroll
                for (int eh = 0; eh < 2; eh++) {
                    float hv[2];
                    #pragma unroll
                    for (int p = 0; p < 2; p++) {
                        int e = eh * 2 + p;
                        float h0 = fmaxf(t0a[i][j][e] + t1a[i][j][e] + b1v[j][p], 0.0f);
                        float h1 = fmaxf(t0a[i][j][e] + t2a[i][j][e] + b1v[j][p], 0.0f);
                        hv[p] = fmaf(att[i][j][e], h0 - h1, h1);
                    }
                    int row = wm * 32 + i * 16 + g + eh * 8;
                    __half* d = (__half*)(smem + SM_A + (colg >> 7) * TILE_HB
                                          + row * TSB + (colg & 127) * 2);
                    *(__half2*)d = __floats2half2_rn(hv[0], hv[1]);
                }
            }
    }

    // =====================================================================
    // L3 + L4: x over K=640 (tiles kc=0..4), N chunks of 128; W4 via mma
    // =====================================================================
    float oat[4] = {0.f, 0.f, 0.f, 0.f};

    for (int nh = 0; nh < 2; nh++) {
        float xacc[2][8][4] = {};
        for (int kc = 0; kc < 5; kc++) {
            __syncthreads();
            {
                const float4* src = (const float4*)(g_w_f16 + (size_t)(4 + kc) * 256 * 136
                                                    + (size_t)nh * 128 * 136);
                float4* d = (float4*)(smem + SM_W);
                for (int i = t; i < 2176; i += 256) d[i] = src[i];
            }
            __syncthreads();
            wgemm1<8>(xacc,
                      sb + SM_A + kc * TILE_HB + wm * 32 * TSB + a_off,
                      sb + SM_W + wn * 64 * TSB + b_off);
        }
        __syncthreads();   // W stage free -> xs buffer

        // xs[row][col] fp16 (relu + b3)
        float b3v[8][2];
        #pragma unroll
        for (int j = 0; j < 8; j++) {
            b3v[j][0] = bs[512 + nh * 128 + wn * 64 + j * 8 + 2 * tq];
            b3v[j][1] = bs[512 + nh * 128 + wn * 64 + j * 8 + 2 * tq + 1];
        }
        #pragma unroll
        for (int i = 0; i < 2; i++)
            #pragma unroll
            for (int j = 0; j < 8; j++) {
                int col = wn * 64 + j * 8 + 2 * tq;
                #pragma unroll
                for (int eh = 0; eh < 2; eh++) {
                    float x0 = fmaxf(xacc[i][j][eh * 2]     + b3v[j][0], 0.0f);
                    float x1 = fmaxf(xacc[i][j][eh * 2 + 1] + b3v[j][1], 0.0f);
                    int row = wm * 32 + i * 16 + g + eh * 8;
                    *(__half2*)((__half*)(smem + SM_W) + row * 136 + col) =
                        __floats2half2_rn(x0, x1);
                }
            }
        __syncthreads();

        // L4: each warp one m16n8 tile, rows wid*16..+15, K=128
        const uint32_t aX  = sb + SM_W + wid * 16 * TSB + a_off;
        const uint32_t bW4 = sb + SM_W4H + nh * 8 * TSB + b_off2;
        #pragma unroll
        for (int kb = 0; kb < 8; kb++) {
            uint32_t af[4], bf[2];
            ldsm4(af, aX + kb * 32);
            ldsm2(bf, bW4 + kb * 32);
            mma16816(oat, af, bf[0], bf[1]);
        }
    }

    // final: bias + tanh, fp32 out
    {
        float bb0 = bs[768 + 2 * tq], bb1 = bs[768 + 2 * tq + 1];
        size_t row = (size_t)cta * 128 + wid * 16 + g;
        float2 r0 = make_float2(tanhf(oat[0] + bb0), tanhf(oat[1] + bb1));
        float2 r1 = make_float2(tanhf(oat[2] + bb0), tanhf(oat[3] + bb1));
        *(float2*)&out[row * 8 + 2 * tq]       = r0;
        *(float2*)&out[(row + 8) * 8 + 2 * tq] = r1;
    }
}

// ---------------------------------------------------------------------------
// kernel_launch — 2 launches, graph-capturable, allocation-free.
// Inputs: state, W1, b1, W2, b2, W3, b3, W4, b4
// ---------------------------------------------------------------------------
extern "C" void kernel_launch(void* const* d_in, const int* in_sizes, int n_in,
                              void* d_out, int out_size)
{
    const float* state = (const float*)d_in[0];
    const float* W1    = (const float*)d_in[1];
    const float* b1    = (const float*)d_in[2];
    const float* W2    = (const float*)d_in[3];
    const float* b2    = (const float*)d_in[4];
    const float* W3    = (const float*)d_in[5];
    const float* b3    = (const float*)d_in[6];
    const float* W4    = (const float*)d_in[7];
    const float* b4    = (const float*)d_in[8];
    float* out = (float*)d_out;

    cudaFuncSetAttribute(actor_main,
                         cudaFuncAttributeMaxDynamicSharedMemorySize, SMEM_BYTES);

    convert_weights<<<9, 256>>>(W1, W2, W3);
    actor_main<<<NCTA, 256, SMEM_BYTES>>>(state, b1, b2, b3, W4, b4, out);
}

// round 12
// speedup vs baseline: 11.1462x; 1.3145x over previous
#include <cuda_runtime.h>
#include <cuda_fp16.h>
#include <math.h>
#include <stdint.h>

// ---------------------------------------------------------------------------
// Actor_Soft_Attention: B=65536, IN=128, HID=256, OUT=8
// mma.sync m16n8k16 fp16/fp32, cp.async double-buffered weight pipeline,
// XOR-swizzled 256B-row tiles, L4 fused from register C-fragments.
//
// pre-kernel: weights -> 18 pre-swizzled [128][128] fp16 stage blobs + W4 blob
// main (512 CTAs x 128 rows, 256 thr):
//   stages 0..7  : L1 per 64-ch chunk: W2 stage -> att, W1 stage -> h_i tiles
//   stages 8..17 : L3 x[128x256] over K=640 {h0,h1,s0,s1,s2} x 2 N-halves
//   at each N-half end: L4 out += x-frag @ W4 (mma from regs)
//   final: cross-warp reduce, tanh, store.
// ---------------------------------------------------------------------------

#define TILE   32768                   // 128 rows x 256B
#define NCTA   512

#define SM_A   0                       // 5 tiles: h0,h1,s0,s1,s2
#define SM_W   (5 * TILE)              // 163840: two 32KB stage buffers
#define SM_W4  (7 * TILE)              // 229376: [8][128] fp16 W4 (per nh)
#define SMEM_BYTES (SM_W4 + 2048)      // 231424

__device__ __align__(16) __half g_wstage[18 * 16384];  // 18 stage blobs
__device__ __align__(16) __half g_w4[2 * 1024];        // 2 x [8][128]

// swizzled byte offset inside a [128 rows][128 halves] tile (256B rows)
__host__ __device__ __forceinline__ uint32_t swz(int r, int ch) {
    return (uint32_t)(r * 256 + ((((ch >> 3) ^ (r & 7)) << 4)) + (ch & 7) * 2);
}

// ---------------- warp primitives ----------------
__device__ __forceinline__ uint32_t smem_u32(const void* p) {
    uint32_t a;
    asm("{ .reg .u64 t; cvta.to.shared.u64 t, %1; cvt.u32.u64 %0, t; }" : "=r"(a) : "l"(p));
    return a;
}
__device__ __forceinline__ void ldsm4(uint32_t* r, uint32_t a) {
    asm volatile("ldmatrix.sync.aligned.m8n8.x4.shared.b16 {%0,%1,%2,%3}, [%4];"
        : "=r"(r[0]), "=r"(r[1]), "=r"(r[2]), "=r"(r[3]) : "r"(a));
}
__device__ __forceinline__ void ldsm2(uint32_t* r, uint32_t a) {
    asm volatile("ldmatrix.sync.aligned.m8n8.x2.shared.b16 {%0,%1}, [%2];"
        : "=r"(r[0]), "=r"(r[1]) : "r"(a));
}
__device__ __forceinline__ void mma16816(float (&c)[4], const uint32_t a[4],
                                         uint32_t b0, uint32_t b1) {
    asm volatile("mma.sync.aligned.m16n8k16.row.col.f32.f16.f16.f32 "
        "{%0,%1,%2,%3}, {%4,%5,%6,%7}, {%8,%9}, {%0,%1,%2,%3};"
        : "+f"(c[0]), "+f"(c[1]), "+f"(c[2]), "+f"(c[3])
        : "r"(a[0]), "r"(a[1]), "r"(a[2]), "r"(a[3]), "r"(b0), "r"(b1));
}
__device__ __forceinline__ uint32_t packh2(float x, float y) {
    __half2 h = __floats2half2_rn(x, y);
    return *(uint32_t*)&h;
}
// 32KB stage prefetch, one commit group
__device__ __forceinline__ void prefetch32k(uint32_t dst, const char* src, int t) {
    #pragma unroll
    for (int i = 0; i < 8; i++) {
        asm volatile("cp.async.cg.shared.global [%0], [%1], 16;"
            :: "r"(dst + (uint32_t)((t + 256 * i) * 16)), "l"(src + (t + 256 * i) * 16));
    }
    asm volatile("cp.async.commit_group;" ::: "memory");
}
#define CP_WAIT_ALL() asm volatile("cp.async.wait_group 0;" ::: "memory")

// C[32 x NT8*8] += A(32 rows,K=128) * W(NT8*8 n-rows,K=128)^T
template<int NT8>
__device__ __forceinline__ void wgemm1(float (&acc)[2][NT8][4],
    uint32_t aBase, int ax, int aHi, uint32_t bBase, int bx, int bHi)
{
    #pragma unroll
    for (int kb = 0; kb < 8; kb++) {
        uint32_t ka  = (uint32_t)(((((kb << 1) | aHi) ^ ax) << 4));
        uint32_t kbb = (uint32_t)(((((kb << 1) | bHi) ^ bx) << 4));
        uint32_t af[2][4], bf[NT8 / 2][4];
        ldsm4(af[0], aBase + ka);
        ldsm4(af[1], aBase + 4096 + ka);
        #pragma unroll
        for (int p = 0; p < NT8 / 2; p++) ldsm4(bf[p], bBase + p * 4096 + kbb);
        #pragma unroll
        for (int i = 0; i < 2; i++)
            #pragma unroll
            for (int j = 0; j < NT8; j++)
                mma16816(acc[i][j], af[i], bf[j >> 1][(j & 1) * 2], bf[j >> 1][(j & 1) * 2 + 1]);
    }
}
// two A tiles sharing one W tile (32 n-rows)
__device__ __forceinline__ void wgemm2(float (&c1)[2][4][4], float (&c2)[2][4][4],
    uint32_t a1, uint32_t a2, int ax, int aHi, uint32_t bBase, int bx, int bHi)
{
    #pragma unroll
    for (int kb = 0; kb < 8; kb++) {
        uint32_t ka  = (uint32_t)(((((kb << 1) | aHi) ^ ax) << 4));
        uint32_t kbb = (uint32_t)(((((kb << 1) | bHi) ^ bx) << 4));
        uint32_t f1[2][4], f2[2][4], bf[2][4];
        ldsm4(f1[0], a1 + ka);         ldsm4(f1[1], a1 + 4096 + ka);
        ldsm4(f2[0], a2 + ka);         ldsm4(f2[1], a2 + 4096 + ka);
        ldsm4(bf[0], bBase + kbb);     ldsm4(bf[1], bBase + 4096 + kbb);
        #pragma unroll
        for (int i = 0; i < 2; i++)
            #pragma unroll
            for (int j = 0; j < 4; j++) {
                uint32_t b0 = bf[j >> 1][(j & 1) * 2], b1 = bf[j >> 1][(j & 1) * 2 + 1];
                mma16816(c1[i][j], f1[i], b0, b1);
                mma16816(c2[i][j], f2[i], b0, b1);
            }
    }
}

// ---------------- weight pre-conversion ----------------
__global__ void convert_weights(const float* __restrict__ W1, const float* __restrict__ W2,
                                const float* __restrict__ W3, const float* __restrict__ W4)
{
    const int s = blockIdx.x, t = threadIdx.x;
    if (s < 18) {
        char* dst = (char*)(g_wstage + (size_t)s * 16384);
        for (int i = t; i < 4096; i += 256) {
            int r = i >> 5, kq = (i & 31) * 4;
            float4 v;
            if (s < 8) {
                int c0 = s >> 1;
                const float* src = (s & 1) ? W1 : W2;
                int wr = c0 * 64 + (r & 63);
                int wk = ((r >> 6) << 7) + kq;
                v = *(const float4*)(src + (size_t)wr * 256 + wk);
            } else {
                int u = s - 8, nh = u / 5, kc = u % 5;
                v = *(const float4*)(W3 + (size_t)(nh * 128 + r) * 640 + kc * 128 + kq);
            }
            char* d = dst + swz(r, kq);
            *(__half2*)d       = __floats2half2_rn(v.x, v.y);
            *(__half2*)(d + 4) = __floats2half2_rn(v.z, v.w);
        }
    } else {
        // W4 blobs: per nh [8 rows][128 halves], swizzled
        for (int i = t; i < 512; i += 256) {
            int idx = i * 4, nh = idx >> 10, rem = idx & 1023, o = rem >> 7, k = rem & 127;
            float4 v = *(const float4*)(W4 + (size_t)o * 256 + nh * 128 + k);
            char* d = (char*)(g_w4 + nh * 1024) + swz(o, k);
            *(__half2*)d       = __floats2half2_rn(v.x, v.y);
            *(__half2*)(d + 4) = __floats2half2_rn(v.z, v.w);
        }
    }
}

// ---------------- main kernel ----------------
__global__ __launch_bounds__(256, 1)
void actor_main(const float* __restrict__ state,
                const float* __restrict__ b1, const float* __restrict__ b2,
                const float* __restrict__ b3, const float* __restrict__ b4,
                float* __restrict__ out)
{
    extern __shared__ char smem[];
    const uint32_t sb = smem_u32(smem);
    const int t = threadIdx.x, wid = t >> 5, l = t & 31;
    const int wm = wid & 3, wn = wid >> 2;
    const int g = l >> 2, tq = l & 3;
    const int cta = blockIdx.x;

    // ldmatrix lane geometry
    const int aRow = l & 15, aHi = l >> 4, ax = l & 7;
    const int bRow = (l & 7) + ((l >> 4) & 1) * 8, bHi = (l >> 3) & 1, bx = l & 7;

    // ---- pipeline prologue: stage0 + W4(nh0) prefetch, then state staging ----
    prefetch32k(sb + SM_W, (const char*)g_wstage, t);
    if (t < 128)
        asm volatile("cp.async.cg.shared.global [%0], [%1], 16;"
            :: "r"(sb + SM_W4 + (uint32_t)(t * 16)), "l"((const char*)g_w4 + t * 16));
    asm volatile("cp.async.commit_group;" ::: "memory");

    {   // state -> swizzled fp16 tiles 2,3,4
        const float4* gs = (const float4*)(state + (size_t)cta * 128 * 384);
        for (int i4 = t; i4 < 12288; i4 += 256) {
            int r = i4 / 96, cq = (i4 % 96) * 4;
            float4 v = gs[i4];
            char* d = smem + SM_A + (2 + (cq >> 7)) * TILE + swz(r, cq & 127);
            *(__half2*)d       = __floats2half2_rn(v.x, v.y);
            *(__half2*)(d + 4) = __floats2half2_rn(v.z, v.w);
        }
    }

    // per-warp fragment bases
    const uint32_t aS0 = sb + SM_A + 2 * TILE + (uint32_t)((wm * 32 + aRow) * 256);
    const uint32_t aS1 = aS0 + TILE, aS2 = aS0 + 2 * TILE;

    // =====================================================================
    // L1 pipeline: stages 0..7 (per c0: W2 stage even, W1 stage odd)
    // =====================================================================
    float att[2][4][4];
    for (int s = 0; s < 8; s++) {
        CP_WAIT_ALL();
        __syncthreads();
        prefetch32k(sb + SM_W + (uint32_t)(((s + 1) & 1) * TILE),
                    (const char*)g_wstage + (size_t)(s + 1) * TILE, t);
        const uint32_t wb  = sb + SM_W + (uint32_t)((s & 1) * TILE);
        const uint32_t bWa = wb + (uint32_t)((wn * 32 + bRow) * 256);
        const uint32_t bWb = bWa + 64 * 256;
        const int c0 = s >> 1;

        float p0[2][4][4] = {}, p1[2][4][4] = {}, p2[2][4][4] = {};
        wgemm1<4>(p0, aS0, ax, aHi, bWa, bx, bHi);
        wgemm2(p1, p2, aS1, aS2, ax, aHi, bWb, bx, bHi);

        if (!(s & 1)) {
            // W2 stage -> attention coefficient
            #pragma unroll
            for (int j = 0; j < 4; j++) {
                int colg = c0 * 64 + wn * 32 + j * 8 + 2 * tq;
                float bb0 = __ldg(&b2[colg]), bb1 = __ldg(&b2[colg + 1]);
                #pragma unroll
                for (int i = 0; i < 2; i++)
                    #pragma unroll
                    for (int e = 0; e < 4; e++) {
                        float bb = (e & 1) ? bb1 : bb0;
                        float e0 = fmaxf(p0[i][j][e] + p1[i][j][e] + bb, 0.0f);
                        float e1 = fmaxf(p0[i][j][e] + p2[i][j][e] + bb, 0.0f);
                        att[i][j][e] = __fdividef(1.0f, 1.0f + __expf(e1 - e0));
                    }
            }
        } else {
            // W1 stage -> h_i into tiles 0/1
            #pragma unroll
            for (int j = 0; j < 4; j++) {
                int colg = c0 * 64 + wn * 32 + j * 8 + 2 * tq;
                float bb0 = __ldg(&b1[colg]), bb1 = __ldg(&b1[colg + 1]);
                #pragma unroll
                for (int i = 0; i < 2; i++)
                    #pragma unroll
                    for (int eh = 0; eh < 2; eh++) {
                        float hv[2];
                        #pragma unroll
                        for (int p = 0; p < 2; p++) {
                            int e = eh * 2 + p;
                            float bb = p ? bb1 : bb0;
                            float h0 = fmaxf(p0[i][j][e] + p1[i][j][e] + bb, 0.0f);
                            float h1 = fmaxf(p0[i][j][e] + p2[i][j][e] + bb, 0.0f);
                            hv[p] = fmaf(att[i][j][e], h0 - h1, h1);
                        }
                        int row = wm * 32 + i * 16 + g + eh * 8;
                        char* d = smem + SM_A + (colg >> 7) * TILE + swz(row, colg & 127);
                        *(__half2*)d = __floats2half2_rn(hv[0], hv[1]);
                    }
            }
        }
    }

    // =====================================================================
    // L3 + L4 pipeline: stages 8..17 (nh = (s-8)/5, kc = (s-8)%5)
    // =====================================================================
    float oat[2][4] = {};
    float xacc[2][8][4];
    for (int s = 8; s < 18; s++) {
        CP_WAIT_ALL();
        __syncthreads();
        if (s < 17)
            prefetch32k(sb + SM_W + (uint32_t)(((s + 1) & 1) * TILE),
                        (const char*)g_wstage + (size_t)(s + 1) * TILE, t);
        const uint32_t wb = sb + SM_W + (uint32_t)((s & 1) * TILE);
        const int u = s - 8, nh = u / 5, kc = u % 5;

        if (kc == 0) {
            #pragma unroll
            for (int i = 0; i < 2; i++)
                #pragma unroll
                for (int j = 0; j < 8; j++)
                    #pragma unroll
                    for (int e = 0; e < 4; e++) xacc[i][j][e] = 0.0f;
        }
        if (s == 13 && t < 128) {   // reload W4h for nh=1 (used at s=17)
            float4 v = *(const float4*)((const char*)g_w4 + 2048 + t * 16);
            *(float4*)(smem + SM_W4 + t * 16) = v;
        }

        wgemm1<8>(xacc,
                  sb + SM_A + kc * TILE + (uint32_t)((wm * 32 + aRow) * 256), ax, aHi,
                  wb + (uint32_t)((wn * 64 + bRow) * 256), bx, bHi);

        if (kc == 4) {
            // L4: relu+b3, pack C-frags as A-frags, mma against W4h
            float b3v[8][2];
            #pragma unroll
            for (int j = 0; j < 8; j++) {
                int c = nh * 128 + wn * 64 + j * 8 + 2 * tq;
                b3v[j][0] = __ldg(&b3[c]);
                b3v[j][1] = __ldg(&b3[c + 1]);
            }
            #pragma unroll
            for (int i = 0; i < 2; i++)
                #pragma unroll
                for (int j0 = 0; j0 < 8; j0 += 2) {
                    uint32_t af[4];
                    af[0] = packh2(fmaxf(xacc[i][j0][0]     + b3v[j0][0],     0.0f),
                                   fmaxf(xacc[i][j0][1]     + b3v[j0][1],     0.0f));
                    af[1] = packh2(fmaxf(xacc[i][j0][2]     + b3v[j0][0],     0.0f),
                                   fmaxf(xacc[i][j0][3]     + b3v[j0][1],     0.0f));
                    af[2] = packh2(fmaxf(xacc[i][j0 + 1][0] + b3v[j0 + 1][0], 0.0f),
                                   fmaxf(xacc[i][j0 + 1][1] + b3v[j0 + 1][1], 0.0f));
                    af[3] = packh2(fmaxf(xacc[i][j0 + 1][2] + b3v[j0 + 1][0], 0.0f),
                                   fmaxf(xacc[i][j0 + 1][3] + b3v[j0 + 1][1], 0.0f));
                    int kbw = wn * 4 + (j0 >> 1);
                    uint32_t bAddr = sb + SM_W4 + (uint32_t)((l & 7) * 256)
                                   + (uint32_t)(((((kbw << 1) | bHi) ^ (l & 7)) << 4));
                    uint32_t bf[2];
                    ldsm2(bf, bAddr);
                    mma16816(oat[i], af, bf[0], bf[1]);
                }
        }
    }

    // =====================================================================
    // final: cross-warp (wn) reduction, bias, tanh, store
    // =====================================================================
    __syncthreads();
    float* red = (float*)(smem + SM_W);   // 4KB, buffers free now
    if (wn == 1) {
        #pragma unroll
        for (int i = 0; i < 2; i++) {
            int r0 = wm * 32 + i * 16 + g;
            *(float2*)&red[r0 * 8 + 2 * tq]       = make_float2(oat[i][0], oat[i][1]);
            *(float2*)&red[(r0 + 8) * 8 + 2 * tq] = make_float2(oat[i][2], oat[i][3]);
        }
    }
    __syncthreads();
    if (wn == 0) {
        float bb0 = __ldg(&b4[2 * tq]), bb1 = __ldg(&b4[2 * tq + 1]);
        #pragma unroll
        for (int i = 0; i < 2; i++) {
            int r0 = wm * 32 + i * 16 + g;
            size_t gr = (size_t)cta * 128 + r0;
            float2 s0 = *(float2*)&red[r0 * 8 + 2 * tq];
            float2 s1 = *(float2*)&red[(r0 + 8) * 8 + 2 * tq];
            *(float2*)&out[gr * 8 + 2 * tq] =
                make_float2(tanhf(oat[i][0] + s0.x + bb0), tanhf(oat[i][1] + s0.y + bb1));
            *(float2*)&out[(gr + 8) * 8 + 2 * tq] =
                make_float2(tanhf(oat[i][2] + s1.x + bb0), tanhf(oat[i][3] + s1.y + bb1));
        }
    }
}

// ---------------------------------------------------------------------------
// kernel_launch — 2 launches, graph-capturable, allocation-free.
// Inputs: state, W1, b1, W2, b2, W3, b3, W4, b4
// ---------------------------------------------------------------------------
extern "C" void kernel_launch(void* const* d_in, const int* in_sizes, int n_in,
                              void* d_out, int out_size)
{
    const float* state = (const float*)d_in[0];
    const float* W1    = (const float*)d_in[1];
    const float* b1    = (const float*)d_in[2];
    const float* W2    = (const float*)d_in[3];
    const float* b2    = (const float*)d_in[4];
    const float* W3    = (const float*)d_in[5];
    const float* b3    = (const float*)d_in[6];
    const float* W4    = (const float*)d_in[7];
    const float* b4    = (const float*)d_in[8];
    float* out = (float*)d_out;

    cudaFuncSetAttribute(actor_main,
                         cudaFuncAttributeMaxDynamicSharedMemorySize, SMEM_BYTES);

    convert_weights<<<19, 256>>>(W1, W2, W3, W4);
    actor_main<<<NCTA, 256, SMEM_BYTES>>>(state, b1, b2, b3, b4, out);
}